// round 1
// baseline (speedup 1.0000x reference)
#include <cuda_runtime.h>
#include <cstdint>

// GestureRNN: 2-layer ReLU RNN, B=4096, T=512, IN=10, H=32, NCLS=9.
// Strategy: one warp per batch element; lane j owns hidden unit j.
// All weight rows live in registers as packed f32x2 pairs; h-state is
// broadcast via per-warp shared memory, read as 128-bit loads that
// directly yield packed (h[k], h[k+1]) operands for fma.rn.f32x2.

typedef unsigned long long ull;

__device__ __forceinline__ ull ffma2(ull a, ull b, ull c) {
    ull d;
    asm("fma.rn.f32x2 %0, %1, %2, %3;" : "=l"(d) : "l"(a), "l"(b), "l"(c));
    return d;
}

__device__ __forceinline__ float hsum2(ull a) {
    return __uint_as_float((unsigned)a) + __uint_as_float((unsigned)(a >> 32));
}

struct __align__(16) WarpBuf {
    float x[12];    // x[10], x[11] stay 0 forever (zero-padded input pair)
    float h1[32];
    float h2[32];
    float pad[4];
};

static constexpr int T_STEPS = 512;
static constexpr int BATCH   = 4096;
static constexpr int IN_DIM  = 10;
static constexpr int NCLS    = 9;
static constexpr int WARPS   = 4;

__global__ void __launch_bounds__(WARPS * 32, 3) rnn_fused_kernel(
    const float* __restrict__ x,
    const float* __restrict__ Wih0, const float* __restrict__ Whh0,
    const float* __restrict__ bih0, const float* __restrict__ bhh0,
    const float* __restrict__ Wih1, const float* __restrict__ Whh1,
    const float* __restrict__ bih1, const float* __restrict__ bhh1,
    const float* __restrict__ Wfc,  const float* __restrict__ bfc,
    float* __restrict__ out)
{
    __shared__ WarpBuf buf[WARPS];

    const int w   = threadIdx.x >> 5;
    const int lid = threadIdx.x & 31;
    const int b   = blockIdx.x * WARPS + w;
    WarpBuf& wb = buf[w];

    // ---- per-lane weight rows, packed as f32x2 pairs in registers ----
    ull w0[16], wi1[16], wh1[16], wx[5];
    {
        const ulonglong2* p0 = (const ulonglong2*)(Whh0 + lid * 32);
        const ulonglong2* p1 = (const ulonglong2*)(Wih1 + lid * 32);
        const ulonglong2* p2 = (const ulonglong2*)(Whh1 + lid * 32);
#pragma unroll
        for (int m = 0; m < 8; m++) {
            ulonglong2 a = p0[m]; w0[2*m]  = a.x; w0[2*m+1]  = a.y;
            ulonglong2 c = p1[m]; wi1[2*m] = c.x; wi1[2*m+1] = c.y;
            ulonglong2 d = p2[m]; wh1[2*m] = d.x; wh1[2*m+1] = d.y;
        }
        const ull* px = (const ull*)(Wih0 + lid * IN_DIM);  // 40B*lid -> 8B aligned
#pragma unroll
        for (int m = 0; m < 5; m++) wx[m] = px[m];
    }
    const float b0 = bih0[lid] + bhh0[lid];
    const float b1 = bih1[lid] + bhh1[lid];

    // ---- init state ----
    wb.h1[lid] = 0.f;
    wb.h2[lid] = 0.f;
    if (lid < 12) wb.x[lid] = 0.f;

    const float* xb = x + (size_t)b * (T_STEPS * IN_DIM);
    float rx = (lid < IN_DIM) ? xb[lid] : 0.f;   // prefetch x for t=0
    __syncwarp();

    const ulonglong2* xp  = (const ulonglong2*)wb.x;
    const ulonglong2* h1p = (const ulonglong2*)wb.h1;
    const ulonglong2* h2p = (const ulonglong2*)wb.h2;

    for (int t = 0; t < T_STEPS; t++) {
        if (lid < IN_DIM) wb.x[lid] = rx;
        __syncwarp();  // publishes x_t and prev-step h2

        // input projection: xp[j] = sum_i x[i] * Wih0[j,i]
        ulonglong2 q0 = xp[0];                 // (x0,x1),(x2,x3)
        ulonglong2 q1 = xp[1];                 // (x4,x5),(x6,x7)
        ull        xa = *(const ull*)(wb.x + 8);  // (x8,x9)
        ull accA = ffma2(wx[0], q0.x, (ull)0);
        ull accB = ffma2(wx[1], q0.y, (ull)0);
        accA = ffma2(wx[2], q1.x, accA);
        accB = ffma2(wx[3], q1.y, accB);
        accA = ffma2(wx[4], xa,   accA);

        // prefetch next step's x while the FMAs run
        {
            int tn = (t + 1 < T_STEPS) ? (t + 1) : t;
            if (lid < IN_DIM) rx = xb[tn * IN_DIM + lid];
        }

        // layer 0 recurrence: + sum_k h1_old[k] * Whh0[j,k]
#pragma unroll
        for (int m = 0; m < 8; m++) {
            ulonglong2 q = h1p[m];
            accA = ffma2(w0[2*m],   q.x, accA);
            accB = ffma2(w0[2*m+1], q.y, accB);
        }
        float h1n = fmaxf(b0 + hsum2(accA) + hsum2(accB), 0.f);

        __syncwarp();          // everyone done reading h1_old
        wb.h1[lid] = h1n;
        __syncwarp();          // h1_new visible to all lanes

        // layer 1: sum_k h1_new[k]*Wih1[j,k] + sum_k h2_old[k]*Whh1[j,k]
        ull aA = 0ull, aB = 0ull;
#pragma unroll
        for (int m = 0; m < 8; m++) {
            ulonglong2 q = h1p[m];
            aA = ffma2(wi1[2*m],   q.x, aA);
            aB = ffma2(wi1[2*m+1], q.y, aB);
        }
#pragma unroll
        for (int m = 0; m < 8; m++) {
            ulonglong2 q = h2p[m];
            aA = ffma2(wh1[2*m],   q.x, aA);
            aB = ffma2(wh1[2*m+1], q.y, aB);
        }
        float h2n = fmaxf(b1 + hsum2(aA) + hsum2(aB), 0.f);

        __syncwarp();          // everyone done reading h2_old
        wb.h2[lid] = h2n;      // published by the syncwarp at loop top
    }
    __syncwarp();

    // classifier head on last h2: out[b,c] = b_fc[c] + sum_j h2[j]*Wfc[c,j]
    if (lid < NCLS) {
        float o = bfc[lid];
        const float* wr = Wfc + lid * 32;
#pragma unroll
        for (int j = 0; j < 32; j++) o += wb.h2[j] * wr[j];
        out[(size_t)b * NCLS + lid] = o;
    }
}

extern "C" void kernel_launch(void* const* d_in, const int* in_sizes, int n_in,
                              void* d_out, int out_size)
{
    const float* x    = (const float*)d_in[0];
    const float* Wih0 = (const float*)d_in[1];
    const float* Whh0 = (const float*)d_in[2];
    const float* bih0 = (const float*)d_in[3];
    const float* bhh0 = (const float*)d_in[4];
    const float* Wih1 = (const float*)d_in[5];
    const float* Whh1 = (const float*)d_in[6];
    const float* bih1 = (const float*)d_in[7];
    const float* bhh1 = (const float*)d_in[8];
    const float* Wfc  = (const float*)d_in[9];
    const float* bfc  = (const float*)d_in[10];
    float* out = (float*)d_out;

    rnn_fused_kernel<<<BATCH / WARPS, WARPS * 32>>>(
        x, Wih0, Whh0, bih0, bhh0, Wih1, Whh1, bih1, bhh1, Wfc, bfc, out);
}